// round 4
// baseline (speedup 1.0000x reference)
#include <cuda_runtime.h>
#include <cuda_bf16.h>

#define NNODES 50000
#define NEDGES 600000
#define CHUNK  1024
#define NCHUNK 49   // ceil(50000/1024)

// ---------------- scratch (device globals) -----------------------------------
__device__ int g_is64;
__device__ int g_cnt [NNODES];
__device__ int g_off [NNODES];
__device__ int g_cur [NNODES];
__device__ int g_src32[NEDGES];
__device__ int g_dst32[NEDGES];
__device__ int g_eidx [NEDGES];
__device__ int g_chunksum[64];
__device__ int g_chunkoff[64];
__device__ __align__(16) float g_agg1[NNODES * 128];  // mean of x[src] at dst
__device__ __align__(16) float g_h   [NNODES * 128];  // layer1 output (post relu)
__device__ __align__(16) float g_p   [NNODES * 64];   // h @ Wl2
__device__ __align__(16) float g_q   [NNODES * 64];   // h @ Wr2 + bl2

// ---------------- dtype detect: int64 edge_index has zero high words ---------
__global__ void detect_kernel(const int* __restrict__ ei32) {
    int allzero = 1;
    #pragma unroll
    for (int i = 0; i < 64; i++)
        if (ei32[2 * i + 1] != 0) allzero = 0;
    g_is64 = allzero;
}

// ---------------- CSR build ---------------------------------------------------
__global__ void zero_cnt_kernel() {
    int i = blockIdx.x * blockDim.x + threadIdx.x;
    if (i < NNODES) g_cnt[i] = 0;
}

__global__ void hist_kernel(const void* __restrict__ ei) {
    int e = blockIdx.x * blockDim.x + threadIdx.x;
    if (e >= NEDGES) return;
    int s, d;
    if (g_is64) {
        const long long* e64 = (const long long*)ei;
        s = (int)e64[e];
        d = (int)e64[NEDGES + e];
    } else {
        const int* e32 = (const int*)ei;
        s = e32[e];
        d = e32[NEDGES + e];
    }
    s = min(max(s, 0), NNODES - 1);
    d = min(max(d, 0), NNODES - 1);
    g_src32[e] = s;
    g_dst32[e] = d;
    atomicAdd(&g_cnt[d], 1);
}

__global__ void scan_p1_kernel() {   // per-chunk sums
    __shared__ int sm[CHUNK];
    int tid = threadIdx.x;
    int idx = blockIdx.x * CHUNK + tid;
    sm[tid] = (idx < NNODES) ? g_cnt[idx] : 0;
    __syncthreads();
    #pragma unroll
    for (int s = CHUNK / 2; s > 0; s >>= 1) {
        if (tid < s) sm[tid] += sm[tid + s];
        __syncthreads();
    }
    if (tid == 0) g_chunksum[blockIdx.x] = sm[0];
}

__global__ void scan_p2_kernel() {   // exclusive scan of chunk sums
    __shared__ int sm[64];
    int tid = threadIdx.x;
    sm[tid] = (tid < NCHUNK) ? g_chunksum[tid] : 0;
    __syncthreads();
    if (tid == 0) {
        int run = 0;
        for (int i = 0; i < NCHUNK; i++) { int v = sm[i]; sm[i] = run; run += v; }
    }
    __syncthreads();
    if (tid < NCHUNK) g_chunkoff[tid] = sm[tid];
}

__global__ void scan_p3_kernel() {   // per-chunk exclusive scan + offset
    __shared__ int sm[CHUNK];
    int tid = threadIdx.x;
    int idx = blockIdx.x * CHUNK + tid;
    int v = (idx < NNODES) ? g_cnt[idx] : 0;
    sm[tid] = v;
    __syncthreads();
    #pragma unroll
    for (int d = 1; d < CHUNK; d <<= 1) {
        int t = (tid >= d) ? sm[tid - d] : 0;
        __syncthreads();
        sm[tid] += t;
        __syncthreads();
    }
    if (idx < NNODES) {
        int off = g_chunkoff[blockIdx.x] + sm[tid] - v;   // exclusive
        g_off[idx] = off;
        g_cur[idx] = off;
    }
}

__global__ void fill_kernel() {
    int e = blockIdx.x * blockDim.x + threadIdx.x;
    if (e >= NEDGES) return;
    int d = g_dst32[e];
    int pos = atomicAdd(&g_cur[d], 1);
    if (pos >= 0 && pos < NEDGES) g_eidx[pos] = g_src32[e];
}

// ---------------- gather layer 1: warp per node, mean of x[src] -------------
__global__ void gather1_kernel(const float4* __restrict__ x4) {
    int w    = (blockIdx.x * blockDim.x + threadIdx.x) >> 5;
    int lane = threadIdx.x & 31;
    if (w >= NNODES) return;
    int beg = g_off[w];
    int c   = g_cnt[w];
    float4 acc = make_float4(0.f, 0.f, 0.f, 0.f);
    int i = 0;
    for (; i + 1 < c; i += 2) {
        int s0 = g_eidx[beg + i];
        int s1 = g_eidx[beg + i + 1];
        float4 v0 = x4[s0 * 32 + lane];
        float4 v1 = x4[s1 * 32 + lane];
        acc.x += v0.x + v1.x; acc.y += v0.y + v1.y;
        acc.z += v0.z + v1.z; acc.w += v0.w + v1.w;
    }
    if (i < c) {
        int s0 = g_eidx[beg + i];
        float4 v0 = x4[s0 * 32 + lane];
        acc.x += v0.x; acc.y += v0.y; acc.z += v0.z; acc.w += v0.w;
    }
    float rd = 1.0f / (float)max(c, 1);
    acc.x *= rd; acc.y *= rd; acc.z *= rd; acc.w *= rd;
    ((float4*)g_agg1)[w * 32 + lane] = acc;
}

// ---------------- GEMM1: h = relu([agg1 ; x] @ [Wl1;Wr1] + bl1) --------------
// BM=64, BN=128, K=256. 256 threads, 8x4 tile/thread.
// SMEM: Ws[256][128] (128KB) + As[64][256] (64KB) = 192KB.
__global__ void gemm1_kernel(const float4* __restrict__ x4,
                             const float4* __restrict__ Wl1,   // [128][32] f4
                             const float4* __restrict__ Wr1,   // [128][32] f4
                             const float4* __restrict__ bl1) { // [32] f4
    extern __shared__ float sm[];
    float* Ws = sm;                 // 256*128
    float* As = sm + 256 * 128;     // 64*256
    int tid = threadIdx.x;
    int tx = tid & 31, ty = tid >> 5;
    int m0 = blockIdx.x * 64;

    float4* Ws4 = (float4*)Ws;
    #pragma unroll
    for (int i = tid; i < 8192; i += 256) {
        int k = i >> 5, c = i & 31;
        Ws4[i] = (k < 128) ? Wl1[k * 32 + c] : Wr1[(k - 128) * 32 + c];
    }
    float4* As4 = (float4*)As;
    const float4* agg4 = (const float4*)g_agg1;
    #pragma unroll
    for (int i = tid; i < 4096; i += 256) {
        int r = i >> 6, c = i & 63;
        int m = m0 + r;
        float4 v = make_float4(0.f, 0.f, 0.f, 0.f);
        if (m < NNODES)
            v = (c < 32) ? agg4[m * 32 + c] : x4[m * 32 + (c - 32)];
        As4[i] = v;
    }
    __syncthreads();

    float acc[8][4] = {};
    #pragma unroll 4
    for (int k = 0; k < 256; k++) {
        float4 b = ((const float4*)(Ws + k * 128))[tx];
        float a[8];
        #pragma unroll
        for (int i = 0; i < 8; i++) a[i] = As[(ty * 8 + i) * 256 + k];
        #pragma unroll
        for (int i = 0; i < 8; i++) {
            acc[i][0] += a[i] * b.x;
            acc[i][1] += a[i] * b.y;
            acc[i][2] += a[i] * b.z;
            acc[i][3] += a[i] * b.w;
        }
    }

    float4 bias = bl1[tx];
    float4* h4 = (float4*)g_h;
    #pragma unroll
    for (int i = 0; i < 8; i++) {
        int m = m0 + ty * 8 + i;
        if (m < NNODES) {
            float4 o;
            o.x = fmaxf(acc[i][0] + bias.x, 0.f);
            o.y = fmaxf(acc[i][1] + bias.y, 0.f);
            o.z = fmaxf(acc[i][2] + bias.z, 0.f);
            o.w = fmaxf(acc[i][3] + bias.w, 0.f);
            h4[m * 32 + tx] = o;
        }
    }
}

// ---------------- GEMM2: p = h@Wl2 ; q = h@Wr2 + bl2 -------------------------
// BM=64, BN=128 (cols 0..63 -> p, 64..127 -> q), K=128.
// SMEM: Ws[128][128] (64KB) + As[64][128] (32KB) = 96KB.
__global__ void gemm2_kernel(const float4* __restrict__ Wl2,   // [128][16] f4
                             const float4* __restrict__ Wr2,   // [128][16] f4
                             const float4* __restrict__ bl2) { // [16] f4
    extern __shared__ float sm[];
    float* Ws = sm;                 // 128*128
    float* As = sm + 128 * 128;     // 64*128
    int tid = threadIdx.x;
    int tx = tid & 31, ty = tid >> 5;
    int m0 = blockIdx.x * 64;

    float4* Ws4 = (float4*)Ws;
    #pragma unroll
    for (int i = tid; i < 4096; i += 256) {
        int k = i >> 5, c = i & 31;
        Ws4[i] = (c < 16) ? Wl2[k * 16 + c] : Wr2[k * 16 + (c - 16)];
    }
    float4* As4 = (float4*)As;
    const float4* h4 = (const float4*)g_h;
    #pragma unroll
    for (int i = tid; i < 2048; i += 256) {
        int r = i >> 5, c = i & 31;
        int m = m0 + r;
        As4[i] = (m < NNODES) ? h4[m * 32 + c] : make_float4(0.f, 0.f, 0.f, 0.f);
    }
    __syncthreads();

    float acc[8][4] = {};
    #pragma unroll 4
    for (int k = 0; k < 128; k++) {
        float4 b = ((const float4*)(Ws + k * 128))[tx];
        float a[8];
        #pragma unroll
        for (int i = 0; i < 8; i++) a[i] = As[(ty * 8 + i) * 128 + k];
        #pragma unroll
        for (int i = 0; i < 8; i++) {
            acc[i][0] += a[i] * b.x;
            acc[i][1] += a[i] * b.y;
            acc[i][2] += a[i] * b.z;
            acc[i][3] += a[i] * b.w;
        }
    }

    float4* p4 = (float4*)g_p;
    float4* q4 = (float4*)g_q;
    if (tx < 16) {
        #pragma unroll
        for (int i = 0; i < 8; i++) {
            int m = m0 + ty * 8 + i;
            if (m < NNODES)
                p4[m * 16 + tx] = make_float4(acc[i][0], acc[i][1], acc[i][2], acc[i][3]);
        }
    } else {
        float4 bias = bl2[tx - 16];
        #pragma unroll
        for (int i = 0; i < 8; i++) {
            int m = m0 + ty * 8 + i;
            if (m < NNODES)
                q4[m * 16 + (tx - 16)] = make_float4(acc[i][0] + bias.x, acc[i][1] + bias.y,
                                                     acc[i][2] + bias.z, acc[i][3] + bias.w);
        }
    }
}

// ---------------- gather layer 2 + log_softmax (fused) -----------------------
// warp per node; lane holds classes {2*lane, 2*lane+1}
__global__ void gather2_final_kernel(float* __restrict__ out) {
    int w    = (blockIdx.x * blockDim.x + threadIdx.x) >> 5;
    int lane = threadIdx.x & 31;
    if (w >= NNODES) return;
    int beg = g_off[w];
    int c   = g_cnt[w];
    const float2* p2 = (const float2*)g_p;
    float2 acc = make_float2(0.f, 0.f);
    int i = 0;
    for (; i + 1 < c; i += 2) {
        int s0 = g_eidx[beg + i];
        int s1 = g_eidx[beg + i + 1];
        float2 v0 = p2[s0 * 32 + lane];
        float2 v1 = p2[s1 * 32 + lane];
        acc.x += v0.x + v1.x;
        acc.y += v0.y + v1.y;
    }
    if (i < c) {
        int s0 = g_eidx[beg + i];
        float2 v0 = p2[s0 * 32 + lane];
        acc.x += v0.x; acc.y += v0.y;
    }
    float rd = 1.0f / (float)max(c, 1);
    float2 q = ((const float2*)g_q)[w * 32 + lane];
    float v0 = acc.x * rd + q.x;
    float v1 = acc.y * rd + q.y;

    float mx = fmaxf(v0, v1);
    #pragma unroll
    for (int o = 16; o; o >>= 1) mx = fmaxf(mx, __shfl_xor_sync(0xffffffffu, mx, o));
    float s = expf(v0 - mx) + expf(v1 - mx);
    #pragma unroll
    for (int o = 16; o; o >>= 1) s += __shfl_xor_sync(0xffffffffu, s, o);
    float ls = logf(s) + mx;

    ((float2*)out)[w * 32 + lane] = make_float2(v0 - ls, v1 - ls);
}

// ---------------- launch ------------------------------------------------------
extern "C" void kernel_launch(void* const* d_in, const int* in_sizes, int n_in,
                              void* d_out, int out_size) {
    const float4* x4   = (const float4*)d_in[0];
    const void*   ei   = d_in[1];
    const float4* Wl1  = (const float4*)d_in[2];
    const float4* bl1  = (const float4*)d_in[3];
    const float4* Wr1  = (const float4*)d_in[4];
    const float4* Wl2  = (const float4*)d_in[5];
    const float4* bl2  = (const float4*)d_in[6];
    const float4* Wr2  = (const float4*)d_in[7];
    float*        out  = (float*)d_out;

    cudaFuncSetAttribute(gemm1_kernel, cudaFuncAttributeMaxDynamicSharedMemorySize, 196608);
    cudaFuncSetAttribute(gemm2_kernel, cudaFuncAttributeMaxDynamicSharedMemorySize, 98304);

    detect_kernel<<<1, 1>>>((const int*)ei);
    zero_cnt_kernel<<<(NNODES + 255) / 256, 256>>>();
    hist_kernel<<<(NEDGES + 255) / 256, 256>>>(ei);
    scan_p1_kernel<<<NCHUNK, CHUNK>>>();
    scan_p2_kernel<<<1, 64>>>();
    scan_p3_kernel<<<NCHUNK, CHUNK>>>();
    fill_kernel<<<(NEDGES + 255) / 256, 256>>>();

    gather1_kernel<<<(NNODES * 32 + 255) / 256, 256>>>(x4);
    gemm1_kernel<<<(NNODES + 63) / 64, 256, 196608>>>(x4, Wl1, Wr1, bl1);
    gemm2_kernel<<<(NNODES + 63) / 64, 256, 98304>>>(Wl2, Wr2, bl2);
    gather2_final_kernel<<<(NNODES * 32 + 255) / 256, 256>>>(out);
}

// round 5
// speedup vs baseline: 1.1425x; 1.1425x over previous
#include <cuda_runtime.h>
#include <cuda_bf16.h>

#define NNODES 50000
#define NEDGES 600000
#define CHUNK  1024
#define NCHUNK 49   // ceil(50000/1024)

// ---------------- scratch (device globals) -----------------------------------
__device__ int g_is64;
__device__ int g_cnt [NNODES];
__device__ int g_off [NNODES];
__device__ int g_cur [NNODES];
__device__ int g_src32[NEDGES];
__device__ int g_dst32[NEDGES];
__device__ int g_eidx [NEDGES];
__device__ int g_chunksum[64];
__device__ int g_chunkoff[64];
__device__ __align__(16) float g_agg1[NNODES * 128];  // mean of x[src] at dst
__device__ __align__(16) float g_h   [NNODES * 128];  // layer1 output (post relu)
__device__ __align__(16) float g_p   [NNODES * 64];   // h @ Wl2
__device__ __align__(16) float g_q   [NNODES * 64];   // h @ Wr2 + bl2

// ---------------- f32x2 helpers -----------------------------------------------
typedef unsigned long long ull;
__device__ __forceinline__ ull pk2(float x, float y) {
    ull r; asm("mov.b64 %0, {%1, %2};" : "=l"(r) : "f"(x), "f"(y)); return r;
}
__device__ __forceinline__ ull pkdup(float x) {
    ull r; asm("mov.b64 %0, {%1, %1};" : "=l"(r) : "f"(x)); return r;
}
__device__ __forceinline__ void ffma2(ull& d, ull a, ull b) {
    asm("fma.rn.f32x2 %0, %1, %2, %0;" : "+l"(d) : "l"(a), "l"(b));
}
__device__ __forceinline__ float2 unpk(ull v) {
    float2 r; asm("mov.b64 {%0, %1}, %2;" : "=f"(r.x), "=f"(r.y) : "l"(v)); return r;
}

// ---------------- dtype detect: int64 edge_index has zero high words ---------
__global__ void detect_kernel(const int* __restrict__ ei32) {
    int allzero = 1;
    #pragma unroll
    for (int i = 0; i < 64; i++)
        if (ei32[2 * i + 1] != 0) allzero = 0;
    g_is64 = allzero;
}

// ---------------- CSR build ---------------------------------------------------
__global__ void zero_cnt_kernel() {
    int i = blockIdx.x * blockDim.x + threadIdx.x;
    if (i < NNODES) g_cnt[i] = 0;
}

__global__ void hist_kernel(const void* __restrict__ ei) {
    int e = blockIdx.x * blockDim.x + threadIdx.x;
    if (e >= NEDGES) return;
    int s, d;
    if (g_is64) {
        const long long* e64 = (const long long*)ei;
        s = (int)e64[e];
        d = (int)e64[NEDGES + e];
    } else {
        const int* e32 = (const int*)ei;
        s = e32[e];
        d = e32[NEDGES + e];
    }
    s = min(max(s, 0), NNODES - 1);
    d = min(max(d, 0), NNODES - 1);
    g_src32[e] = s;
    g_dst32[e] = d;
    atomicAdd(&g_cnt[d], 1);
}

__global__ void scan_p1_kernel() {   // per-chunk sums
    __shared__ int sm[CHUNK];
    int tid = threadIdx.x;
    int idx = blockIdx.x * CHUNK + tid;
    sm[tid] = (idx < NNODES) ? g_cnt[idx] : 0;
    __syncthreads();
    #pragma unroll
    for (int s = CHUNK / 2; s > 0; s >>= 1) {
        if (tid < s) sm[tid] += sm[tid + s];
        __syncthreads();
    }
    if (tid == 0) g_chunksum[blockIdx.x] = sm[0];
}

__global__ void scan_p2_kernel() {   // exclusive scan of chunk sums
    __shared__ int sm[64];
    int tid = threadIdx.x;
    sm[tid] = (tid < NCHUNK) ? g_chunksum[tid] : 0;
    __syncthreads();
    if (tid == 0) {
        int run = 0;
        for (int i = 0; i < NCHUNK; i++) { int v = sm[i]; sm[i] = run; run += v; }
    }
    __syncthreads();
    if (tid < NCHUNK) g_chunkoff[tid] = sm[tid];
}

__global__ void scan_p3_kernel() {   // per-chunk exclusive scan + offset
    __shared__ int sm[CHUNK];
    int tid = threadIdx.x;
    int idx = blockIdx.x * CHUNK + tid;
    int v = (idx < NNODES) ? g_cnt[idx] : 0;
    sm[tid] = v;
    __syncthreads();
    #pragma unroll
    for (int d = 1; d < CHUNK; d <<= 1) {
        int t = (tid >= d) ? sm[tid - d] : 0;
        __syncthreads();
        sm[tid] += t;
        __syncthreads();
    }
    if (idx < NNODES) {
        int off = g_chunkoff[blockIdx.x] + sm[tid] - v;   // exclusive
        g_off[idx] = off;
        g_cur[idx] = off;
    }
}

__global__ void fill_kernel() {
    int e = blockIdx.x * blockDim.x + threadIdx.x;
    if (e >= NEDGES) return;
    int d = g_dst32[e];
    int pos = atomicAdd(&g_cur[d], 1);
    if (pos >= 0 && pos < NEDGES) g_eidx[pos] = g_src32[e];
}

// ---------------- gather layer 1: warp per node, mean of x[src] -------------
__global__ void gather1_kernel(const float4* __restrict__ x4) {
    int w    = (blockIdx.x * blockDim.x + threadIdx.x) >> 5;
    int lane = threadIdx.x & 31;
    if (w >= NNODES) return;
    int beg = g_off[w];
    int c   = g_cnt[w];
    float4 acc = make_float4(0.f, 0.f, 0.f, 0.f);
    int i = 0;
    for (; i + 1 < c; i += 2) {
        int s0 = g_eidx[beg + i];
        int s1 = g_eidx[beg + i + 1];
        float4 v0 = x4[s0 * 32 + lane];
        float4 v1 = x4[s1 * 32 + lane];
        acc.x += v0.x + v1.x; acc.y += v0.y + v1.y;
        acc.z += v0.z + v1.z; acc.w += v0.w + v1.w;
    }
    if (i < c) {
        int s0 = g_eidx[beg + i];
        float4 v0 = x4[s0 * 32 + lane];
        acc.x += v0.x; acc.y += v0.y; acc.z += v0.z; acc.w += v0.w;
    }
    float rd = 1.0f / (float)max(c, 1);
    acc.x *= rd; acc.y *= rd; acc.z *= rd; acc.w *= rd;
    ((float4*)g_agg1)[w * 32 + lane] = acc;
}

// ---------------- GEMM1: h = relu([agg1 ; x] @ [Wl1;Wr1] + bl1) --------------
// BM=64, BN=128, K=256. 256 threads, 8x4 tile/thread, f32x2 math.
// SMEM: Ws[256][128] (128KB) + As[64][256] (64KB) = 192KB.
__global__ void __launch_bounds__(256, 1)
gemm1_kernel(const float4* __restrict__ x4,
             const float4* __restrict__ Wl1,   // [128][32] f4
             const float4* __restrict__ Wr1,   // [128][32] f4
             const float4* __restrict__ bl1) { // [32] f4
    extern __shared__ float sm[];
    float* Ws = sm;                 // 256*128
    float* As = sm + 256 * 128;     // 64*256
    int tid = threadIdx.x;
    int tx = tid & 31, ty = tid >> 5;
    int m0 = blockIdx.x * 64;

    float4* Ws4 = (float4*)Ws;
    #pragma unroll
    for (int i = tid; i < 8192; i += 256) {
        int k = i >> 5, c = i & 31;
        Ws4[i] = (k < 128) ? Wl1[k * 32 + c] : Wr1[(k - 128) * 32 + c];
    }
    float4* As4 = (float4*)As;
    const float4* agg4 = (const float4*)g_agg1;
    #pragma unroll
    for (int i = tid; i < 4096; i += 256) {
        int r = i >> 6, c = i & 63;
        int m = m0 + r;
        float4 v = make_float4(0.f, 0.f, 0.f, 0.f);
        if (m < NNODES)
            v = (c < 32) ? agg4[m * 32 + c] : x4[m * 32 + (c - 32)];
        As4[i] = v;
    }
    __syncthreads();

    ull acc01[8] = {}, acc23[8] = {};
    #pragma unroll 2
    for (int k = 0; k < 256; k += 4) {
        float4 a[8];
        #pragma unroll
        for (int i = 0; i < 8; i++) a[i] = As4[(ty * 8 + i) * 64 + (k >> 2)];
        #pragma unroll
        for (int j = 0; j < 4; j++) {
            float4 b = Ws4[(k + j) * 32 + tx];
            ull b01 = pk2(b.x, b.y);
            ull b23 = pk2(b.z, b.w);
            #pragma unroll
            for (int i = 0; i < 8; i++) {
                float aij = (j == 0) ? a[i].x : (j == 1) ? a[i].y : (j == 2) ? a[i].z : a[i].w;
                ull aa = pkdup(aij);
                ffma2(acc01[i], aa, b01);
                ffma2(acc23[i], aa, b23);
            }
        }
    }

    float4 bias = bl1[tx];
    float4* h4 = (float4*)g_h;
    #pragma unroll
    for (int i = 0; i < 8; i++) {
        int m = m0 + ty * 8 + i;
        if (m < NNODES) {
            float2 v01 = unpk(acc01[i]);
            float2 v23 = unpk(acc23[i]);
            float4 o;
            o.x = fmaxf(v01.x + bias.x, 0.f);
            o.y = fmaxf(v01.y + bias.y, 0.f);
            o.z = fmaxf(v23.x + bias.z, 0.f);
            o.w = fmaxf(v23.y + bias.w, 0.f);
            h4[m * 32 + tx] = o;
        }
    }
}

// ---------------- GEMM2: p = h@Wl2 ; q = h@Wr2 + bl2 -------------------------
// BM=64, BN=128 (cols 0..63 -> p, 64..127 -> q), K=128, f32x2 math.
// SMEM: Ws[128][128] (64KB) + As[64][128] (32KB) = 96KB.
__global__ void __launch_bounds__(256, 1)
gemm2_kernel(const float4* __restrict__ Wl2,   // [128][16] f4
             const float4* __restrict__ Wr2,   // [128][16] f4
             const float4* __restrict__ bl2) { // [16] f4
    extern __shared__ float sm[];
    float* Ws = sm;                 // 128*128
    float* As = sm + 128 * 128;     // 64*128
    int tid = threadIdx.x;
    int tx = tid & 31, ty = tid >> 5;
    int m0 = blockIdx.x * 64;

    float4* Ws4 = (float4*)Ws;
    #pragma unroll
    for (int i = tid; i < 4096; i += 256) {
        int k = i >> 5, c = i & 31;
        Ws4[i] = (c < 16) ? Wl2[k * 16 + c] : Wr2[k * 16 + (c - 16)];
    }
    float4* As4 = (float4*)As;
    const float4* h4 = (const float4*)g_h;
    #pragma unroll
    for (int i = tid; i < 2048; i += 256) {
        int r = i >> 5, c = i & 31;
        int m = m0 + r;
        As4[i] = (m < NNODES) ? h4[m * 32 + c] : make_float4(0.f, 0.f, 0.f, 0.f);
    }
    __syncthreads();

    ull acc01[8] = {}, acc23[8] = {};
    #pragma unroll 2
    for (int k = 0; k < 128; k += 4) {
        float4 a[8];
        #pragma unroll
        for (int i = 0; i < 8; i++) a[i] = As4[(ty * 8 + i) * 32 + (k >> 2)];
        #pragma unroll
        for (int j = 0; j < 4; j++) {
            float4 b = Ws4[(k + j) * 32 + tx];
            ull b01 = pk2(b.x, b.y);
            ull b23 = pk2(b.z, b.w);
            #pragma unroll
            for (int i = 0; i < 8; i++) {
                float aij = (j == 0) ? a[i].x : (j == 1) ? a[i].y : (j == 2) ? a[i].z : a[i].w;
                ull aa = pkdup(aij);
                ffma2(acc01[i], aa, b01);
                ffma2(acc23[i], aa, b23);
            }
        }
    }

    float4* p4 = (float4*)g_p;
    float4* q4 = (float4*)g_q;
    if (tx < 16) {
        #pragma unroll
        for (int i = 0; i < 8; i++) {
            int m = m0 + ty * 8 + i;
            if (m < NNODES) {
                float2 v01 = unpk(acc01[i]);
                float2 v23 = unpk(acc23[i]);
                p4[m * 16 + tx] = make_float4(v01.x, v01.y, v23.x, v23.y);
            }
        }
    } else {
        float4 bias = bl2[tx - 16];
        #pragma unroll
        for (int i = 0; i < 8; i++) {
            int m = m0 + ty * 8 + i;
            if (m < NNODES) {
                float2 v01 = unpk(acc01[i]);
                float2 v23 = unpk(acc23[i]);
                q4[m * 16 + (tx - 16)] = make_float4(v01.x + bias.x, v01.y + bias.y,
                                                     v23.x + bias.z, v23.y + bias.w);
            }
        }
    }
}

// ---------------- gather layer 2 + log_softmax (fused) -----------------------
// warp per node; lane holds classes {2*lane, 2*lane+1}
__global__ void gather2_final_kernel(float* __restrict__ out) {
    int w    = (blockIdx.x * blockDim.x + threadIdx.x) >> 5;
    int lane = threadIdx.x & 31;
    if (w >= NNODES) return;
    int beg = g_off[w];
    int c   = g_cnt[w];
    const float2* p2 = (const float2*)g_p;
    float2 acc = make_float2(0.f, 0.f);
    int i = 0;
    for (; i + 1 < c; i += 2) {
        int s0 = g_eidx[beg + i];
        int s1 = g_eidx[beg + i + 1];
        float2 v0 = p2[s0 * 32 + lane];
        float2 v1 = p2[s1 * 32 + lane];
        acc.x += v0.x + v1.x;
        acc.y += v0.y + v1.y;
    }
    if (i < c) {
        int s0 = g_eidx[beg + i];
        float2 v0 = p2[s0 * 32 + lane];
        acc.x += v0.x; acc.y += v0.y;
    }
    float rd = 1.0f / (float)max(c, 1);
    float2 q = ((const float2*)g_q)[w * 32 + lane];
    float v0 = acc.x * rd + q.x;
    float v1 = acc.y * rd + q.y;

    float mx = fmaxf(v0, v1);
    #pragma unroll
    for (int o = 16; o; o >>= 1) mx = fmaxf(mx, __shfl_xor_sync(0xffffffffu, mx, o));
    float s = expf(v0 - mx) + expf(v1 - mx);
    #pragma unroll
    for (int o = 16; o; o >>= 1) s += __shfl_xor_sync(0xffffffffu, s, o);
    float ls = logf(s) + mx;

    ((float2*)out)[w * 32 + lane] = make_float2(v0 - ls, v1 - ls);
}

// ---------------- launch ------------------------------------------------------
extern "C" void kernel_launch(void* const* d_in, const int* in_sizes, int n_in,
                              void* d_out, int out_size) {
    const float4* x4   = (const float4*)d_in[0];
    const void*   ei   = d_in[1];
    const float4* Wl1  = (const float4*)d_in[2];
    const float4* bl1  = (const float4*)d_in[3];
    const float4* Wr1  = (const float4*)d_in[4];
    const float4* Wl2  = (const float4*)d_in[5];
    const float4* bl2  = (const float4*)d_in[6];
    const float4* Wr2  = (const float4*)d_in[7];
    float*        out  = (float*)d_out;

    cudaFuncSetAttribute(gemm1_kernel, cudaFuncAttributeMaxDynamicSharedMemorySize, 196608);
    cudaFuncSetAttribute(gemm2_kernel, cudaFuncAttributeMaxDynamicSharedMemorySize, 98304);

    detect_kernel<<<1, 1>>>((const int*)ei);
    zero_cnt_kernel<<<(NNODES + 255) / 256, 256>>>();
    hist_kernel<<<(NEDGES + 255) / 256, 256>>>(ei);
    scan_p1_kernel<<<NCHUNK, CHUNK>>>();
    scan_p2_kernel<<<1, 64>>>();
    scan_p3_kernel<<<NCHUNK, CHUNK>>>();
    fill_kernel<<<(NEDGES + 255) / 256, 256>>>();

    gather1_kernel<<<(NNODES * 32 + 255) / 256, 256>>>(x4);
    gemm1_kernel<<<(NNODES + 63) / 64, 256, 196608>>>(x4, Wl1, Wr1, bl1);
    gemm2_kernel<<<(NNODES + 63) / 64, 256, 98304>>>(Wl2, Wr2, bl2);
    gather2_final_kernel<<<(NNODES * 32 + 255) / 256, 256>>>(out);
}